// round 15
// baseline (speedup 1.0000x reference)
#include <cuda_runtime.h>
#include <cstdint>
#include <math.h>

#define Bsz 2
#define Lsz 1024
#define Vsz 50257
#define NT  256
#define NROWS (Bsz * Lsz)
#define NSTAGE 8
#define STAGE_F4 256            // float4 per stage (== NT)
#define NFULL 49                // (Vsz-head)>>2>>8 == 49 for all head in 0..3
#define BETA 0.04f
#define EPS_LOW 0.2f
#define EPS_HIGH 0.2f

// accumulators: [0]=kl_sum [1]=clip_sum [2]=loss_b0 [3]=loss_b1 [4]=mask_b0 [5]=mask_b1
__device__ float g_acc[6];
__device__ unsigned int g_count = 0;

__device__ __forceinline__ float warp_sum(float v) {
    #pragma unroll
    for (int o = 16; o > 0; o >>= 1) v += __shfl_xor_sync(0xFFFFFFFFu, v, o);
    return v;
}

__device__ __forceinline__ void cp_async16(unsigned int smem_addr, const void* gptr) {
    asm volatile("cp.async.cg.shared.global [%0], [%1], 16;\n"
                 :: "r"(smem_addr), "l"(gptr));
}
__device__ __forceinline__ void cp_commit() {
    asm volatile("cp.async.commit_group;\n");
}
__device__ __forceinline__ void cp_wait7() {
    asm volatile("cp.async.wait_group 7;\n");
}

__global__ __launch_bounds__(NT)
void grpo_kernel(const float* __restrict__ logits,
                 const int* __restrict__ cids,
                 const float* __restrict__ adv,
                 const float* __restrict__ old_lp,
                 const float* __restrict__ ref_lp,
                 const int* __restrict__ cmask,
                 float* __restrict__ out) {
    __shared__ float4 buf[NSTAGE * STAGE_F4];     // 32 KB ring

    const int row = blockIdx.x;
    const int b = row >> 10;
    const int l = row & (Lsz - 1);
    const size_t off = ((size_t)(b * (Lsz + 1) + l)) * (size_t)Vsz;
    const float* __restrict__ p = logits + off;
    const int tid = threadIdx.x;

    float s0 = 0.f, s1 = 0.f, s2 = 0.f, s3 = 0.f;

    // head so that p+head is 16B aligned
    const int head = (int)((4 - (off & 3)) & 3);
    if (tid < head) s0 += __expf(p[tid]);

    const int nv = (Vsz - head) >> 2;              // 12563/12564; >>8 == 49 always
    const float4* __restrict__ p4 = (const float4*)(p + head);

    unsigned int smem_base;
    {
        unsigned int a;
        asm("{ .reg .u64 t; cvta.to.shared.u64 t, %1; cvt.u32.u64 %0, t; }"
            : "=r"(a) : "l"((const void*)buf));
        smem_base = a;
    }
    const unsigned int smem_my = smem_base + (unsigned int)tid * 16u;
    const float4* gsrc = p4 + tid;

    // prologue: fill 8 stages
    #pragma unroll
    for (int s = 0; s < NSTAGE; s++) {
        cp_async16(smem_my + (unsigned int)(s * (STAGE_F4 * 16)),
                   (const void*)(gsrc + s * STAGE_F4));
        cp_commit();
    }

    // main: producer==consumer per word -> no barriers
    #pragma unroll 8
    for (int s = 0; s < NFULL - NSTAGE; s++) {
        cp_wait7();
        const int slot = s & (NSTAGE - 1);
        float4 v = buf[slot * STAGE_F4 + tid];
        s0 += __expf(v.x); s1 += __expf(v.y); s2 += __expf(v.z); s3 += __expf(v.w);
        cp_async16(smem_my + (unsigned int)(slot * (STAGE_F4 * 16)),
                   (const void*)(gsrc + (s + NSTAGE) * STAGE_F4));
        cp_commit();
    }
    #pragma unroll
    for (int s = NFULL - NSTAGE; s < NFULL; s++) {
        cp_wait7();
        const int slot = s & (NSTAGE - 1);
        float4 v = buf[slot * STAGE_F4 + tid];
        s0 += __expf(v.x); s1 += __expf(v.y); s2 += __expf(v.z); s3 += __expf(v.w);
        cp_commit();
    }

    // remainder float4s + scalar tail
    for (int i = NFULL * STAGE_F4 + tid; i < nv; i += NT) {
        float4 v = __ldcs(p4 + i);
        s0 += __expf(v.x); s1 += __expf(v.y); s2 += __expf(v.z); s3 += __expf(v.w);
    }
    const int done = head + (nv << 2);
    for (int k = done + tid; k < Vsz; k += NT) s0 += __expf(p[k]);

    float S = (s0 + s1) + (s2 + s3);

    __shared__ float red[NT / 32];
    S = warp_sum(S);
    if ((tid & 31) == 0) red[tid >> 5] = S;
    __syncthreads();
    if (tid != 0) return;

    // ---- thread 0: per-token GRPO terms + global accumulation ----
    float tot = 0.f;
    #pragma unroll
    for (int w = 0; w < NT / 32; w++) tot += red[w];
    float lse = logf(tot);
    float lp  = p[cids[row]] - lse;

    float mk = (float)cmask[row];
    float a  = adv[b];
    float c1 = expf(lp - old_lp[row]);
    float c2 = fminf(fmaxf(c1, 1.0f - EPS_LOW), 1.0f + EPS_HIGH);
    float ptl = -fminf(c1 * a, c2 * a);
    float d  = ref_lp[row] - lp;
    float kl = expf(d) - d - 1.0f;
    ptl += BETA * kl;
    bool clipped = ((c1 < 1.0f - EPS_LOW) && (a < 0.f)) ||
                   ((c1 > 1.0f + EPS_HIGH) && (a > 0.f));

    atomicAdd(&g_acc[0], kl * mk);
    atomicAdd(&g_acc[1], (clipped ? 1.0f : 0.0f) * mk);
    atomicAdd(&g_acc[2 + b], ptl * mk);
    atomicAdd(&g_acc[4 + b], mk);

    __threadfence();
    unsigned int v = atomicAdd(&g_count, 1u);
    if (v == NROWS - 1) {
        g_count = 0;
        // read via atomic to guarantee coherent L2 values
        float kl_s = atomicAdd(&g_acc[0], 0.f);
        float cl_s = atomicAdd(&g_acc[1], 0.f);
        float L0   = atomicAdd(&g_acc[2], 0.f);
        float L1   = atomicAdd(&g_acc[3], 0.f);
        float M0   = atomicAdd(&g_acc[4], 0.f);
        float M1   = atomicAdd(&g_acc[5], 0.f);
        float ms = fmaxf(M0 + M1, 1.0f);
        out[0] = 0.5f * (L0 / fmaxf(M0, 1.0f) + L1 / fmaxf(M1, 1.0f));
        out[1] = kl_s / ms;
        out[2] = cl_s / ms;
        // reset accumulators for the next graph replay
        #pragma unroll
        for (int j = 0; j < 6; j++) g_acc[j] = 0.f;
        __threadfence();
    }
}

extern "C" void kernel_launch(void* const* d_in, const int* in_sizes, int n_in,
                              void* d_out, int out_size) {
    const float* logits = (const float*)d_in[0];
    const int*   cids   = (const int*)d_in[1];
    const float* adv    = (const float*)d_in[2];
    const float* old_lp = (const float*)d_in[3];
    const float* ref_lp = (const float*)d_in[4];
    const int*   cmask  = (const int*)d_in[5];
    float* out = (float*)d_out;

    grpo_kernel<<<NROWS, NT>>>(logits, cids, adv, old_lp, ref_lp, cmask, out);
}

// round 16
// speedup vs baseline: 1.0088x; 1.0088x over previous
#include <cuda_runtime.h>
#include <cstdint>
#include <math.h>

#define Bsz 2
#define Lsz 1024
#define Vsz 50257
#define NT  256
#define NROWS (Bsz * Lsz)
#define NSTAGE 8
#define STAGE_F4 256            // float4 per stage (== NT)
#define NFULL 49                // (Vsz-head)>>2>>8 == 49 for all head in 0..3
#define BETA 0.04f
#define EPS_LOW 0.2f
#define EPS_HIGH 0.2f

// accumulators: [0]=kl_sum [1]=clip_sum [2]=loss_b0 [3]=loss_b1 [4]=mask_b0 [5]=mask_b1
__device__ float g_acc[6];
__device__ unsigned int g_count = 0;

__device__ __forceinline__ float warp_sum(float v) {
    #pragma unroll
    for (int o = 16; o > 0; o >>= 1) v += __shfl_xor_sync(0xFFFFFFFFu, v, o);
    return v;
}

__device__ __forceinline__ void cp_async16(unsigned int smem_addr, const void* gptr) {
    asm volatile("cp.async.cg.shared.global [%0], [%1], 16;\n"
                 :: "r"(smem_addr), "l"(gptr));
}
__device__ __forceinline__ void cp_commit() {
    asm volatile("cp.async.commit_group;\n");
}
__device__ __forceinline__ void cp_wait7() {
    asm volatile("cp.async.wait_group 7;\n");
}

__global__ __launch_bounds__(NT)
void grpo_kernel(const float* __restrict__ logits,
                 const int* __restrict__ cids,
                 const float* __restrict__ adv,
                 const float* __restrict__ old_lp,
                 const float* __restrict__ ref_lp,
                 const int* __restrict__ cmask,
                 float* __restrict__ out) {
    __shared__ float4 buf[NSTAGE * STAGE_F4];     // 32 KB ring

    const int row = blockIdx.x;
    const int b = row >> 10;
    const int l = row & (Lsz - 1);
    const size_t off = ((size_t)(b * (Lsz + 1) + l)) * (size_t)Vsz;
    const float* __restrict__ p = logits + off;
    const int tid = threadIdx.x;

    // ---- thread 0: prefetch all epilogue scalars BEFORE the stream so they
    // are not dependent cold loads on the critical path at the end ----
    float pf_tok = 0.f, pf_old = 0.f, pf_ref = 0.f, pf_adv = 0.f, pf_mk = 0.f;
    if (tid == 0) {
        int cid = __ldg(cids + row);
        pf_tok = __ldg(p + cid);
        pf_old = __ldg(old_lp + row);
        pf_ref = __ldg(ref_lp + row);
        pf_adv = __ldg(adv + b);
        pf_mk  = (float)__ldg(cmask + row);
    }

    float s0 = 0.f, s1 = 0.f, s2 = 0.f, s3 = 0.f;

    // head so that p+head is 16B aligned
    const int head = (int)((4 - (off & 3)) & 3);
    if (tid < head) s0 += __expf(p[tid]);

    const int nv = (Vsz - head) >> 2;              // 12563/12564; >>8 == 49 always
    const float4* __restrict__ p4 = (const float4*)(p + head);

    unsigned int smem_base;
    {
        unsigned int a;
        asm("{ .reg .u64 t; cvta.to.shared.u64 t, %1; cvt.u32.u64 %0, t; }"
            : "=r"(a) : "l"((const void*)buf));
        smem_base = a;
    }
    const unsigned int smem_my = smem_base + (unsigned int)tid * 16u;
    const float4* gsrc = p4 + tid;

    // prologue: fill 8 stages
    #pragma unroll
    for (int s = 0; s < NSTAGE; s++) {
        cp_async16(smem_my + (unsigned int)(s * (STAGE_F4 * 16)),
                   (const void*)(gsrc + s * STAGE_F4));
        cp_commit();
    }

    // issue remainder + scalar-tail loads NOW so they overlap the pipeline
    float4 remv = make_float4(0.f, 0.f, 0.f, 0.f);
    const int remi = NFULL * STAGE_F4 + tid;       // at most one per thread (rem <= 20)
    if (remi < nv) remv = __ldcs(p4 + remi);
    float tailv = 0.f;
    const int done = head + (nv << 2);
    if (done + tid < Vsz) tailv = p[done + tid];   // <=3 threads

    // main: producer==consumer per word -> no barriers
    #pragma unroll 8
    for (int s = 0; s < NFULL - NSTAGE; s++) {
        cp_wait7();
        const int slot = s & (NSTAGE - 1);
        float4 v = buf[slot * STAGE_F4 + tid];
        s0 += __expf(v.x); s1 += __expf(v.y); s2 += __expf(v.z); s3 += __expf(v.w);
        cp_async16(smem_my + (unsigned int)(slot * (STAGE_F4 * 16)),
                   (const void*)(gsrc + (s + NSTAGE) * STAGE_F4));
        cp_commit();
    }
    #pragma unroll
    for (int s = NFULL - NSTAGE; s < NFULL; s++) {
        cp_wait7();
        const int slot = s & (NSTAGE - 1);
        float4 v = buf[slot * STAGE_F4 + tid];
        s0 += __expf(v.x); s1 += __expf(v.y); s2 += __expf(v.z); s3 += __expf(v.w);
        cp_commit();
    }

    // fold prefetched remainder + tail
    if (remi < nv) {
        s0 += __expf(remv.x); s1 += __expf(remv.y);
        s2 += __expf(remv.z); s3 += __expf(remv.w);
    }
    if (done + tid < Vsz) s0 += __expf(tailv);

    float S = (s0 + s1) + (s2 + s3);

    __shared__ float red[NT / 32];
    S = warp_sum(S);
    if ((tid & 31) == 0) red[tid >> 5] = S;
    __syncthreads();
    if (tid != 0) return;

    // ---- thread 0: per-token GRPO terms + global accumulation ----
    float tot = 0.f;
    #pragma unroll
    for (int w = 0; w < NT / 32; w++) tot += red[w];
    float lse = logf(tot);
    float lp  = pf_tok - lse;

    float a  = pf_adv;
    float c1 = expf(lp - pf_old);
    float c2 = fminf(fmaxf(c1, 1.0f - EPS_LOW), 1.0f + EPS_HIGH);
    float ptl = -fminf(c1 * a, c2 * a);
    float d  = pf_ref - lp;
    float kl = expf(d) - d - 1.0f;
    ptl += BETA * kl;
    bool clipped = ((c1 < 1.0f - EPS_LOW) && (a < 0.f)) ||
                   ((c1 > 1.0f + EPS_HIGH) && (a > 0.f));

    atomicAdd(&g_acc[0], kl * pf_mk);
    atomicAdd(&g_acc[1], (clipped ? 1.0f : 0.0f) * pf_mk);
    atomicAdd(&g_acc[2 + b], ptl * pf_mk);
    atomicAdd(&g_acc[4 + b], pf_mk);

    __threadfence();
    unsigned int v = atomicAdd(&g_count, 1u);
    if (v == NROWS - 1) {
        g_count = 0;
        float kl_s = atomicAdd(&g_acc[0], 0.f);
        float cl_s = atomicAdd(&g_acc[1], 0.f);
        float L0   = atomicAdd(&g_acc[2], 0.f);
        float L1   = atomicAdd(&g_acc[3], 0.f);
        float M0   = atomicAdd(&g_acc[4], 0.f);
        float M1   = atomicAdd(&g_acc[5], 0.f);
        float ms = fmaxf(M0 + M1, 1.0f);
        out[0] = 0.5f * (L0 / fmaxf(M0, 1.0f) + L1 / fmaxf(M1, 1.0f));
        out[1] = kl_s / ms;
        out[2] = cl_s / ms;
        #pragma unroll
        for (int j = 0; j < 6; j++) g_acc[j] = 0.f;
        __threadfence();
    }
}

extern "C" void kernel_launch(void* const* d_in, const int* in_sizes, int n_in,
                              void* d_out, int out_size) {
    const float* logits = (const float*)d_in[0];
    const int*   cids   = (const int*)d_in[1];
    const float* adv    = (const float*)d_in[2];
    const float* old_lp = (const float*)d_in[3];
    const float* ref_lp = (const float*)d_in[4];
    const int*   cmask  = (const int*)d_in[5];
    float* out = (float*)d_out;

    grpo_kernel<<<NROWS, NT>>>(logits, cids, adv, old_lp, ref_lp, cmask, out);
}